// round 15
// baseline (speedup 1.0000x reference)
#include <cuda_runtime.h>
#include <cuda_fp16.h>
#include <cstdint>
#include <math.h>

// Problem constants
#define B_   512
#define C_   2048
#define HW_  64
#define CF_  512
#define J_   30
#define D_   15450          // J*(CF+3)
#define JP_  520            // padded joint width (fp16, 1040B, 16B aligned)
#define DP_  (J_ * JP_)     // 15600
#define EPS_ 1e-5f

// Output layout (flattened tuple concat):
// root (512*6) @0, pose (512*126) @3072, shape (512*10) @67584, cam (512*3) @72704

// ---- scratch (static device globals; no allocation APIs) ----
__device__ float g_pooled[B_ * C_];                        // 4 MB
__device__ float g_part[(size_t)15 * B_ * 132];            // partials, stride 132
// feat fp16, padded: [b][j][520]
__device__ __align__(256) __half g_feat_h[(size_t)B_ * DP_];        // 16 MB
// big-head weights fp16 (first 128 outputs), padded: [o][j][520]
__device__ __align__(256) __half g_Wbig[(size_t)128 * DP_];         // 4 MB
// conv W fp16: [m=512][k=2048]
__device__ __align__(256) __half g_Wh[(size_t)512 * 2048];          // 2 MB
// X fp16: [b][c][hw]
__device__ __align__(256) __half g_Xh[(size_t)B_ * C_ * HW_];       // 134 MB

// =================== PTX helpers (sm_80+ ISA only) ===================
__device__ __forceinline__ uint32_t smem_u32(const void* p) {
    uint32_t a;
    asm("{ .reg .u64 t; cvta.to.shared.u64 t, %1; cvt.u32.u64 %0, t; }" : "=r"(a) : "l"(p));
    return a;
}
__device__ __forceinline__ void cpa16(uint32_t dst, const void* src) {
    asm volatile("cp.async.cg.shared.global [%0], [%1], 16;" :: "r"(dst), "l"(src));
}
#define CP_COMMIT() asm volatile("cp.async.commit_group;" ::: "memory")
#define CP_WAIT0()  asm volatile("cp.async.wait_group 0;" ::: "memory")

__device__ __forceinline__ void ldsm_x4(uint32_t (&r)[4], uint32_t addr) {
    asm volatile("ldmatrix.sync.aligned.m8n8.x4.shared.b16 {%0,%1,%2,%3}, [%4];"
        : "=r"(r[0]), "=r"(r[1]), "=r"(r[2]), "=r"(r[3]) : "r"(addr));
}
__device__ __forceinline__ void ldsm_x4t(uint32_t (&r)[4], uint32_t addr) {
    asm volatile("ldmatrix.sync.aligned.m8n8.x4.trans.shared.b16 {%0,%1,%2,%3}, [%4];"
        : "=r"(r[0]), "=r"(r[1]), "=r"(r[2]), "=r"(r[3]) : "r"(addr));
}
__device__ __forceinline__ void mma_f16(float (&c)[4], const uint32_t (&a)[4],
                                        uint32_t b0, uint32_t b1) {
    asm volatile("mma.sync.aligned.m16n8k16.row.col.f32.f16.f16.f32 "
        "{%0,%1,%2,%3}, {%4,%5,%6,%7}, {%8,%9}, {%0,%1,%2,%3};"
        : "+f"(c[0]), "+f"(c[1]), "+f"(c[2]), "+f"(c[3])
        : "r"(a[0]), "r"(a[1]), "r"(a[2]), "r"(a[3]), "r"(b0), "r"(b1));
}

// ============================================================
// K_prep_w: conv_w fp32 -> fp16, [m][k] row-major
// ============================================================
__global__ void __launch_bounds__(256) k_prep_w(const float* __restrict__ Wsrc) {
    int i = blockIdx.x * 256 + threadIdx.x;     // over 512*1024 float2
    int m = i >> 10, c2 = i & 1023;
    float2 v = *(const float2*)(Wsrc + (size_t)m * C_ + 2 * c2);
    __half2 ph; ph.x = __float2half(v.x); ph.y = __float2half(v.y);
    *(__half2*)(g_Wh + (size_t)m * 2048 + 2 * c2) = ph;
}

// ============================================================
// K_prep_rw: root_w(6) + pose_w(0..121) -> fp16 padded [128][j][520]
// ============================================================
__global__ void __launch_bounds__(256) k_prep_rw(const float* __restrict__ rw,
                                                 const float* __restrict__ pw) {
    int idx = blockIdx.x * 256 + threadIdx.x;   // over 128*15600
    if (idx >= 128 * DP_) return;
    int o = idx / DP_, r = idx - o * DP_;
    int j = r / JP_, c = r - j * JP_;
    float v = 0.f;
    if (c < 515) {
        const float* wr = (o < 6) ? (rw + (size_t)o * D_) : (pw + (size_t)(o - 6) * D_);
        v = wr[j * 515 + c];
    }
    g_Wbig[idx] = __float2half(v);
}

// ============================================================
// K_prep_x: img fp32 -> fp16 (same layout) + fused global pool
// ============================================================
__global__ void __launch_bounds__(256) k_prep_x(const float* __restrict__ img) {
    size_t i = (size_t)blockIdx.x * 256 + threadIdx.x;   // over 16.8M float4
    float4 v = ((const float4*)img)[i];
    __half2 a; a.x = __float2half(v.x); a.y = __float2half(v.y);
    __half2 b; b.x = __float2half(v.z); b.y = __float2half(v.w);
    *(uint2*)(g_Xh + i * 4) = make_uint2(*(uint32_t*)&a, *(uint32_t*)&b);
    float s = v.x + v.y + v.z + v.w;
#pragma unroll
    for (int off = 1; off < 16; off <<= 1) s += __shfl_xor_sync(0xffffffffu, s, off);
    if ((threadIdx.x & 15) == 0) g_pooled[i >> 4] = s * (1.0f / 64.0f);
}

// ============================================================
// K0b: shape/cam heads (13 warps, warp per output) + feat tail cols
// ============================================================
__global__ void __launch_bounds__(416) k_heads(
    const float* __restrict__ sw, const float* __restrict__ sb,
    const float* __restrict__ cw, const float* __restrict__ cb,
    const float* __restrict__ coords, float* __restrict__ out) {
    int b = blockIdx.x;
    __shared__ float pr[C_];
    for (int i = threadIdx.x; i < C_; i += 416) pr[i] = g_pooled[b * C_ + i];
    for (int t = threadIdx.x; t < J_ * 8; t += 416) {
        int j = t >> 3, c8 = t & 7;
        float v = (c8 < 3) ? coords[(b * J_ + j) * 3 + c8] : 0.f;
        g_feat_h[(size_t)b * DP_ + j * JP_ + 512 + c8] = __float2half(v);
    }
    __syncthreads();
    int o = threadIdx.x >> 5, l = threadIdx.x & 31;
    const float* wr = (o < 10) ? (sw + (size_t)o * C_) : (cw + (size_t)(o - 10) * C_);
    float s = 0.f;
#pragma unroll 8
    for (int k = l; k < C_; k += 32) s += pr[k] * wr[k];
#pragma unroll
    for (int off = 16; off; off >>= 1) s += __shfl_xor_sync(0xffffffffu, s, off);
    if (l == 0) {
        if (o < 10) out[67584 + b * 10 + o] = s + sb[o];
        else        out[72704 + b * 3 + (o - 10)] = s + cb[o - 10];
    }
}

// ============================================================
// K1: conv GEMM via mma.sync + FUSED bilinear gather -> g_feat_h (fp16)
// CTA: M=128 cf x N=64 (1 batch x 64 hw), K=2048, 32 chunks of 64.
// 256 threads (8 warps: 4m x 2n, warp tile 32x32), 3 CTAs/SM, 2-stage.
// SMEM per stage 27648 B (A 128x144B; B 64x144B); total 55296 B.
// ============================================================
#define A_SZ  18432
#define STG   27648
#define SMEM_CONV (2 * STG)

__global__ void __launch_bounds__(256, 3) k_conv_mma(
    const float* __restrict__ coords, const float* __restrict__ cbias,
    const float* __restrict__ gam, const float* __restrict__ bet,
    const float* __restrict__ mu, const float* __restrict__ var) {
    extern __shared__ __align__(16) char dsm[];
    __shared__ int   s_gi[J_][4];
    __shared__ float s_gw[J_][4];
    const int tid = threadIdx.x;
    const int m0 = blockIdx.x * 128;
    const int b0 = blockIdx.y;             // one batch per CTA
    const uint32_t sbase = smem_u32(dsm);

    float acc[2][4][4];
#pragma unroll
    for (int i = 0; i < 2; i++)
#pragma unroll
        for (int j = 0; j < 4; j++)
#pragma unroll
            for (int r = 0; r < 4; r++) acc[i][j][r] = 0.f;

    auto issue_chunk = [&](int kc, int nb) {
        int k0 = kc * 64;
        uint32_t abase = sbase + nb * STG;
        uint32_t bbase = abase + A_SZ;
        // A: 128 rows x 128B = 1024 cpa16; 4 per thread
#pragma unroll
        for (int t = 0; t < 4; t++) {
            int idx = tid + t * 256;
            int row = idx >> 3, q = idx & 7;
            const __half* src = g_Wh + (size_t)(m0 + row) * 2048 + k0 + q * 8;
            cpa16(abase + row * 144 + q * 16, src);
        }
        // B: 64 k-rows x 128B = 512 cpa16; 2 per thread
#pragma unroll
        for (int t = 0; t < 2; t++) {
            int idx = tid + t * 256;
            int k = idx >> 3, q = idx & 7;
            const __half* src = g_Xh + ((size_t)b0 * C_ + k0 + k) * HW_ + q * 8;
            cpa16(bbase + k * 144 + q * 16, src);
        }
        CP_COMMIT();
    };

    const int w = tid >> 5, lane = tid & 31;
    const int wm = (w >> 1) * 32;          // cf offset
    const int wn = (w & 1) * 32;           // hw offset
    const int lrow = lane & 15, lsel = lane >> 4;

    auto compute = [&](int nb) {
        uint32_t Ah = sbase + nb * STG;
        uint32_t Bh = Ah + A_SZ;
#pragma unroll
        for (int ks = 0; ks < 4; ks++) {
            int acol = (ks * 16 + lsel * 8) * 2;
            int arow = wm + lrow;
            int brow = (ks * 16 + lrow) * 144;
            int bcol0 = (wn + lsel * 8) * 2;
            uint32_t a[2][4], bh[2][4];
#pragma unroll
            for (int i = 0; i < 2; i++) ldsm_x4(a[i], Ah + (arow + i * 16) * 144 + acol);
#pragma unroll
            for (int j = 0; j < 2; j++) ldsm_x4t(bh[j], Bh + brow + bcol0 + j * 32);
#pragma unroll
            for (int i = 0; i < 2; i++)
#pragma unroll
                for (int jj = 0; jj < 4; jj++)
                    mma_f16(acc[i][jj], a[i],
                            bh[jj >> 1][(jj & 1) * 2], bh[jj >> 1][(jj & 1) * 2 + 1]);
        }
    };

    issue_chunk(0, 0);
    CP_WAIT0();
    __syncthreads();

    for (int kc = 0; kc < 32; kc++) {
        int nb = kc & 1;
        if (kc < 31) issue_chunk(kc + 1, nb ^ 1);
        compute(nb);
        if (kc < 31) {
            CP_WAIT0();
            __syncthreads();
        }
    }

    // ======== fused epilogue: BN+ReLU -> smem F tile -> bilinear gather ========
    __syncthreads();
    float* Fs = (float*)dsm;               // [64 hw][128 cf] = 32KB
    {
        int gid = lane >> 2, tig = lane & 3;
#pragma unroll
        for (int i = 0; i < 2; i++) {
            int cfl = wm + i * 16 + gid;
            int cfA = m0 + cfl, cfB = cfA + 8;
            float scA = gam[cfA] * rsqrtf(var[cfA] + EPS_);
            float bbA = bet[cfA] + (cbias[cfA] - mu[cfA]) * scA;
            float scB = gam[cfB] * rsqrtf(var[cfB] + EPS_);
            float bbB = bet[cfB] + (cbias[cfB] - mu[cfB]) * scB;
#pragma unroll
            for (int jj = 0; jj < 4; jj++) {
                int hw = wn + jj * 8 + tig * 2;
                Fs[hw * 128 + cfl]           = fmaxf(fmaf(acc[i][jj][0], scA, bbA), 0.f);
                Fs[(hw + 1) * 128 + cfl]     = fmaxf(fmaf(acc[i][jj][1], scA, bbA), 0.f);
                Fs[hw * 128 + cfl + 8]       = fmaxf(fmaf(acc[i][jj][2], scB, bbB), 0.f);
                Fs[(hw + 1) * 128 + cfl + 8] = fmaxf(fmaf(acc[i][jj][3], scB, bbB), 0.f);
            }
        }
    }
    if (tid < J_) {
        int j = tid;
        float x = coords[(b0 * J_ + j) * 3 + 0];
        float y = coords[(b0 * J_ + j) * 3 + 1];
        float x0f = floorf(x), y0f = floorf(y);
        float wx1 = x - x0f, wy1 = y - y0f;
        float wx0 = 1.f - wx1, wy0 = 1.f - wy1;
        int x0 = (int)x0f, y0 = (int)y0f, x1 = x0 + 1, y1 = y0 + 1;
        int ys[4] = {y0, y0, y1, y1};
        int xs[4] = {x0, x1, x0, x1};
        float ws[4] = {wy0 * wx0, wy0 * wx1, wy1 * wx0, wy1 * wx1};
#pragma unroll
        for (int c = 0; c < 4; c++) {
            bool valid = (xs[c] >= 0) && (xs[c] < 8) && (ys[c] >= 0) && (ys[c] < 8);
            int yc = min(max(ys[c], 0), 7), xc = min(max(xs[c], 0), 7);
            s_gi[j][c] = yc * 8 + xc;
            s_gw[j][c] = valid ? ws[c] : 0.f;
        }
    }
    __syncthreads();
    {
        int jh = tid >> 7, cfl = tid & 127;    // jh: joint half (0..14 / 15..29)
        const float* Fg = Fs + cfl;
        __half* dst = g_feat_h + (size_t)b0 * DP_ + m0 + cfl;
#pragma unroll 5
        for (int j = jh * 15; j < jh * 15 + 15; j++) {
            int i0 = s_gi[j][0], i1 = s_gi[j][1];
            int i2 = s_gi[j][2], i3 = s_gi[j][3];
            float v = s_gw[j][0] * Fg[i0 * 128] + s_gw[j][1] * Fg[i1 * 128]
                    + s_gw[j][2] * Fg[i2 * 128] + s_gw[j][3] * Fg[i3 * 128];
            dst[j * JP_] = __float2half(v);
        }
    }
}

// ============================================================
// K3: big heads via mma.sync. grid (8 b-tiles, 15 joint-pair ksplits).
// CTA: 64 batch x 128 out, K=1040 (2 joints, padded). 128 threads (4 warps
// 2m x 2n, warp tile 32x64). 13 chunks of 80. 2-stage cp.async.
// ============================================================
#define MM_ASZ 11264
#define MM_STG 33792
#define SMEM_MM (2 * MM_STG)

__global__ void __launch_bounds__(128) k_bigmm_mma() {
    extern __shared__ __align__(16) char dsm[];
    const int tid = threadIdx.x;
    const int b0 = blockIdx.x * 64;
    const int ks = blockIdx.y;                 // joint pair
    const size_t kbase = (size_t)ks * 2 * JP_;
    const uint32_t sbase = smem_u32(dsm);

    float acc[2][8][4];
#pragma unroll
    for (int i = 0; i < 2; i++)
#pragma unroll
        for (int j = 0; j < 8; j++)
#pragma unroll
            for (int r = 0; r < 4; r++) acc[i][j][r] = 0.f;

    auto issue_chunk = [&](int kc, int nb) {
        int k0 = kc * 80;
        uint32_t abase = sbase + nb * MM_STG;
        uint32_t bbase = abase + MM_ASZ;
#pragma unroll
        for (int t = 0; t < 5; t++) {
            int idx = tid + t * 128;
            int row = idx / 10, q = idx - row * 10;
            const __half* src = g_feat_h + (size_t)(b0 + row) * DP_ + kbase + k0 + q * 8;
            cpa16(abase + row * 176 + q * 16, src);
        }
#pragma unroll
        for (int t = 0; t < 10; t++) {
            int idx = tid + t * 128;
            int row = idx / 10, q = idx - row * 10;
            const __half* src = g_Wbig + (size_t)row * DP_ + kbase + k0 + q * 8;
            cpa16(bbase + row * 176 + q * 16, src);
        }
        CP_COMMIT();
    };

    const int w = tid >> 5, lane = tid & 31;
    const int wm = (w >> 1) * 32;
    const int wn = (w & 1) * 64;
    const int lrow = lane & 15, lsel = lane >> 4;
    const int bn = (lane & 7) | ((lane >> 1) & 8);
    const int bk = (lane >> 3) & 1;

    auto compute = [&](int nb) {
        uint32_t As = sbase + nb * MM_STG;
        uint32_t Bs = As + MM_ASZ;
#pragma unroll
        for (int ks2 = 0; ks2 < 5; ks2++) {
            uint32_t a[2][4], bh[4][4];
#pragma unroll
            for (int i = 0; i < 2; i++)
                ldsm_x4(a[i], As + (wm + lrow + i * 16) * 176 + (ks2 * 16 + lsel * 8) * 2);
#pragma unroll
            for (int j = 0; j < 4; j++)
                ldsm_x4(bh[j], Bs + (wn + j * 16 + bn) * 176 + (ks2 * 16 + bk * 8) * 2);
#pragma unroll
            for (int i = 0; i < 2; i++)
#pragma unroll
                for (int jj = 0; jj < 8; jj++)
                    mma_f16(acc[i][jj], a[i],
                            bh[jj >> 1][(jj & 1) * 2], bh[jj >> 1][(jj & 1) * 2 + 1]);
        }
    };

    issue_chunk(0, 0);
    CP_WAIT0();
    __syncthreads();
    for (int kc = 0; kc < 13; kc++) {
        int nb = kc & 1;
        if (kc < 12) issue_chunk(kc + 1, nb ^ 1);
        compute(nb);
        if (kc < 12) {
            CP_WAIT0();
            __syncthreads();
        }
    }

    int gid = lane >> 2, tig = lane & 3;
    float* P = g_part + (size_t)ks * B_ * 132;
#pragma unroll
    for (int i = 0; i < 2; i++) {
        int mA = b0 + wm + i * 16 + gid, mB = mA + 8;
#pragma unroll
        for (int jj = 0; jj < 8; jj++) {
            int o = wn + jj * 8 + tig * 2;
            P[(size_t)mA * 132 + o]     = acc[i][jj][0];
            P[(size_t)mA * 132 + o + 1] = acc[i][jj][1];
            P[(size_t)mB * 132 + o]     = acc[i][jj][2];
            P[(size_t)mB * 132 + o + 1] = acc[i][jj][3];
        }
    }
}

// ============================================================
// K_tail: pose outputs 122..125 via ksplit partials. grid (8 btiles, 15 jsplits).
// ============================================================
__global__ void __launch_bounds__(256) k_tail(const float* __restrict__ pw) {
    __shared__ float sw_[4][1030];
    int b0 = blockIdx.x * 64;
    int ks = blockIdx.y;
    int j0 = ks * 2;
    for (int t = threadIdx.x; t < 4 * 1030; t += 256) {
        int o = t / 1030, r = t - o * 1030;
        int jj = r / 515, c = r - jj * 515;
        sw_[o][r] = pw[(size_t)(122 + o) * D_ + (j0 + jj) * 515 + c];
    }
    __syncthreads();
    int b = b0 + (threadIdx.x >> 2), o = threadIdx.x & 3;
    const __half* fb = g_feat_h + (size_t)b * DP_ + (size_t)j0 * JP_;
    float s = 0.f;
#pragma unroll 2
    for (int jj = 0; jj < 2; jj++) {
        const __half* fj = fb + jj * JP_;
        const float* wj = sw_[o] + jj * 515;
#pragma unroll 5
        for (int c = 0; c < 515; c++)
            s += __half2float(fj[c]) * wj[c];
    }
    g_part[((size_t)ks * B_ + b) * 132 + 128 + o] = s;
}

// ============================================================
// K_reduce: sum 15 partials for all 132 outputs, add bias
// ============================================================
__global__ void k_reduce(const float* __restrict__ rb, const float* __restrict__ pb,
                         float* __restrict__ out) {
    int i = blockIdx.x * 256 + threadIdx.x;
    if (i >= B_ * 132) return;
    int b = i / 132, o = i - b * 132;
    float s = 0.f;
#pragma unroll
    for (int ks = 0; ks < 15; ks++) s += g_part[(size_t)ks * B_ * 132 + i];
    if (o < 6) out[b * 6 + o] = s + rb[o];
    else       out[3072 + b * 126 + (o - 6)] = s + pb[o - 6];
}

// ============================================================
extern "C" void kernel_launch(void* const* d_in, const int* in_sizes, int n_in,
                              void* d_out, int out_size) {
    const float* img    = (const float*)d_in[0];
    const float* coords = (const float*)d_in[1];
    const float* conv_w = (const float*)d_in[2];
    const float* conv_b = (const float*)d_in[3];
    const float* gam    = (const float*)d_in[4];
    const float* bet    = (const float*)d_in[5];
    const float* mu     = (const float*)d_in[6];
    const float* var    = (const float*)d_in[7];
    const float* root_w = (const float*)d_in[8];
    const float* root_b = (const float*)d_in[9];
    const float* pose_w = (const float*)d_in[10];
    const float* pose_b = (const float*)d_in[11];
    const float* shp_w  = (const float*)d_in[12];
    const float* shp_b  = (const float*)d_in[13];
    const float* cam_w  = (const float*)d_in[14];
    const float* cam_b  = (const float*)d_in[15];
    float* out = (float*)d_out;

    cudaFuncSetAttribute(k_conv_mma, cudaFuncAttributeMaxDynamicSharedMemorySize, SMEM_CONV);
    cudaFuncSetAttribute(k_bigmm_mma, cudaFuncAttributeMaxDynamicSharedMemorySize, SMEM_MM);

    k_prep_w<<<2048, 256>>>(conv_w);
    k_prep_rw<<<(128 * DP_ + 255) / 256, 256>>>(root_w, pose_w);
    k_prep_x<<<65536, 256>>>(img);                   // also computes g_pooled
    k_heads<<<B_, 416>>>(shp_w, shp_b, cam_w, cam_b, coords, out);
    k_conv_mma<<<dim3(4, 512), 256, SMEM_CONV>>>(coords, conv_b, gam, bet, mu, var);
    k_bigmm_mma<<<dim3(8, 15), 128, SMEM_MM>>>();
    k_tail<<<dim3(8, 15), 256>>>(pose_w);
    k_reduce<<<(B_ * 132 + 255) / 256, 256>>>(root_b, pose_b, out);
}

// round 16
// speedup vs baseline: 1.0577x; 1.0577x over previous
#include <cuda_runtime.h>
#include <cuda_fp16.h>
#include <cstdint>
#include <math.h>

// Problem constants
#define B_   512
#define C_   2048
#define HW_  64
#define CF_  512
#define J_   30
#define D_   15450          // J*(CF+3)
#define JP_  520            // padded joint width (fp16, 1040B, 16B aligned)
#define DP_  (J_ * JP_)     // 15600
#define EPS_ 1e-5f

// Output layout (flattened tuple concat):
// root (512*6) @0, pose (512*126) @3072, shape (512*10) @67584, cam (512*3) @72704

// ---- scratch (static device globals; no allocation APIs) ----
__device__ float g_pooled[B_ * C_];                        // 4 MB
__device__ float g_part[(size_t)15 * B_ * 132];            // partials, stride 132
// feat fp16, padded: [b][j][520]
__device__ __align__(256) __half g_feat_h[(size_t)B_ * DP_];        // 16 MB
// big-head weights fp16 (first 128 outputs), padded: [o][j][520]
__device__ __align__(256) __half g_Wbig[(size_t)128 * DP_];         // 4 MB
// conv W fp16: [m=512][k=2048]
__device__ __align__(256) __half g_Wh[(size_t)512 * 2048];          // 2 MB
// X fp16: [b][c][hw]
__device__ __align__(256) __half g_Xh[(size_t)B_ * C_ * HW_];       // 134 MB

// =================== PTX helpers (sm_80+ ISA only) ===================
__device__ __forceinline__ uint32_t smem_u32(const void* p) {
    uint32_t a;
    asm("{ .reg .u64 t; cvta.to.shared.u64 t, %1; cvt.u32.u64 %0, t; }" : "=r"(a) : "l"(p));
    return a;
}
__device__ __forceinline__ void cpa16(uint32_t dst, const void* src) {
    asm volatile("cp.async.cg.shared.global [%0], [%1], 16;" :: "r"(dst), "l"(src));
}
#define CP_COMMIT() asm volatile("cp.async.commit_group;" ::: "memory")
#define CP_WAIT0()  asm volatile("cp.async.wait_group 0;" ::: "memory")
#define CP_WAIT1()  asm volatile("cp.async.wait_group 1;" ::: "memory")

__device__ __forceinline__ void ldsm_x4(uint32_t (&r)[4], uint32_t addr) {
    asm volatile("ldmatrix.sync.aligned.m8n8.x4.shared.b16 {%0,%1,%2,%3}, [%4];"
        : "=r"(r[0]), "=r"(r[1]), "=r"(r[2]), "=r"(r[3]) : "r"(addr));
}
__device__ __forceinline__ void ldsm_x4t(uint32_t (&r)[4], uint32_t addr) {
    asm volatile("ldmatrix.sync.aligned.m8n8.x4.trans.shared.b16 {%0,%1,%2,%3}, [%4];"
        : "=r"(r[0]), "=r"(r[1]), "=r"(r[2]), "=r"(r[3]) : "r"(addr));
}
__device__ __forceinline__ void mma_f16(float (&c)[4], const uint32_t (&a)[4],
                                        uint32_t b0, uint32_t b1) {
    asm volatile("mma.sync.aligned.m16n8k16.row.col.f32.f16.f16.f32 "
        "{%0,%1,%2,%3}, {%4,%5,%6,%7}, {%8,%9}, {%0,%1,%2,%3};"
        : "+f"(c[0]), "+f"(c[1]), "+f"(c[2]), "+f"(c[3])
        : "r"(a[0]), "r"(a[1]), "r"(a[2]), "r"(a[3]), "r"(b0), "r"(b1));
}

// ============================================================
// K_prep_w: conv_w fp32 -> fp16, [m][k] row-major
// ============================================================
__global__ void __launch_bounds__(256) k_prep_w(const float* __restrict__ Wsrc) {
    int i = blockIdx.x * 256 + threadIdx.x;     // over 512*1024 float2
    int m = i >> 10, c2 = i & 1023;
    float2 v = *(const float2*)(Wsrc + (size_t)m * C_ + 2 * c2);
    __half2 ph; ph.x = __float2half(v.x); ph.y = __float2half(v.y);
    *(__half2*)(g_Wh + (size_t)m * 2048 + 2 * c2) = ph;
}

// ============================================================
// K_prep_rw: root_w(6) + pose_w(0..121) -> fp16 padded [128][j][520]
// ============================================================
__global__ void __launch_bounds__(256) k_prep_rw(const float* __restrict__ rw,
                                                 const float* __restrict__ pw) {
    int idx = blockIdx.x * 256 + threadIdx.x;   // over 128*15600
    if (idx >= 128 * DP_) return;
    int o = idx / DP_, r = idx - o * DP_;
    int j = r / JP_, c = r - j * JP_;
    float v = 0.f;
    if (c < 515) {
        const float* wr = (o < 6) ? (rw + (size_t)o * D_) : (pw + (size_t)(o - 6) * D_);
        v = wr[j * 515 + c];
    }
    g_Wbig[idx] = __float2half(v);
}

// ============================================================
// K_prep_x: img fp32 -> fp16 (same layout) + fused global pool
// ============================================================
__global__ void __launch_bounds__(256) k_prep_x(const float* __restrict__ img) {
    size_t i = (size_t)blockIdx.x * 256 + threadIdx.x;   // over 16.8M float4
    float4 v = ((const float4*)img)[i];
    __half2 a; a.x = __float2half(v.x); a.y = __float2half(v.y);
    __half2 b; b.x = __float2half(v.z); b.y = __float2half(v.w);
    *(uint2*)(g_Xh + i * 4) = make_uint2(*(uint32_t*)&a, *(uint32_t*)&b);
    float s = v.x + v.y + v.z + v.w;
#pragma unroll
    for (int off = 1; off < 16; off <<= 1) s += __shfl_xor_sync(0xffffffffu, s, off);
    if ((threadIdx.x & 15) == 0) g_pooled[i >> 4] = s * (1.0f / 64.0f);
}

// ============================================================
// K0b: shape/cam heads (13 warps, warp per output) + feat tail cols
// ============================================================
__global__ void __launch_bounds__(416) k_heads(
    const float* __restrict__ sw, const float* __restrict__ sb,
    const float* __restrict__ cw, const float* __restrict__ cb,
    const float* __restrict__ coords, float* __restrict__ out) {
    int b = blockIdx.x;
    __shared__ float pr[C_];
    for (int i = threadIdx.x; i < C_; i += 416) pr[i] = g_pooled[b * C_ + i];
    for (int t = threadIdx.x; t < J_ * 8; t += 416) {
        int j = t >> 3, c8 = t & 7;
        float v = (c8 < 3) ? coords[(b * J_ + j) * 3 + c8] : 0.f;
        g_feat_h[(size_t)b * DP_ + j * JP_ + 512 + c8] = __float2half(v);
    }
    __syncthreads();
    int o = threadIdx.x >> 5, l = threadIdx.x & 31;
    const float* wr = (o < 10) ? (sw + (size_t)o * C_) : (cw + (size_t)(o - 10) * C_);
    float s = 0.f;
#pragma unroll 8
    for (int k = l; k < C_; k += 32) s += pr[k] * wr[k];
#pragma unroll
    for (int off = 16; off; off >>= 1) s += __shfl_xor_sync(0xffffffffu, s, off);
    if (l == 0) {
        if (o < 10) out[67584 + b * 10 + o] = s + sb[o];
        else        out[72704 + b * 3 + (o - 10)] = s + cb[o - 10];
    }
}

// ============================================================
// K1: conv GEMM via mma.sync + FUSED bilinear gather -> g_feat_h (fp16)
// CTA: M=128 cf x N=128 (2 batches x 64 hw), K=2048, 32 chunks of 64.
// 256 threads (8 warps: 4m x 2n, warp tile 32x64), 2 CTAs/SM.
// 3-stage cp.async pipeline, wait_group 1 (loads run 2 chunks ahead).
// SMEM per stage 35840 B (A 128x144B; B 64x272B); total 107520 B.
// (x2 CTAs = 215KB <= 228KB carveout)
// ============================================================
#define A_SZ  18432
#define STG   35840
#define SMEM_CONV (3 * STG)

__global__ void __launch_bounds__(256, 2) k_conv_mma(
    const float* __restrict__ coords, const float* __restrict__ cbias,
    const float* __restrict__ gam, const float* __restrict__ bet,
    const float* __restrict__ mu, const float* __restrict__ var) {
    extern __shared__ __align__(16) char dsm[];
    __shared__ int   s_gi[2][J_][4];
    __shared__ float s_gw[2][J_][4];
    const int tid = threadIdx.x;
    const int m0 = blockIdx.x * 128;
    const int b0 = blockIdx.y * 2;
    const uint32_t sbase = smem_u32(dsm);

    float acc[2][8][4];
#pragma unroll
    for (int i = 0; i < 2; i++)
#pragma unroll
        for (int j = 0; j < 8; j++)
#pragma unroll
            for (int r = 0; r < 4; r++) acc[i][j][r] = 0.f;

    auto issue_chunk = [&](int kc, int st) {
        int k0 = kc * 64;
        uint32_t abase = sbase + st * STG;
        uint32_t bbase = abase + A_SZ;
#pragma unroll
        for (int t = 0; t < 4; t++) {
            int idx = tid + t * 256;
            int row = idx >> 3, q = idx & 7;
            const __half* src = g_Wh + (size_t)(m0 + row) * 2048 + k0 + q * 8;
            cpa16(abase + row * 144 + q * 16, src);
        }
#pragma unroll
        for (int t = 0; t < 4; t++) {
            int idx = tid + t * 256;
            int k = idx >> 4, r = idx & 15;
            int j = r >> 3, hwq = r & 7;
            const __half* src =
                g_Xh + ((size_t)(b0 + j) * C_ + k0 + k) * HW_ + hwq * 8;
            cpa16(bbase + k * 272 + r * 16, src);
        }
        CP_COMMIT();
    };

    const int w = tid >> 5, lane = tid & 31;
    const int wm = (w >> 1) * 32;
    const int wn = (w & 1) * 64;
    const int lrow = lane & 15, lsel = lane >> 4;

    auto compute = [&](int st) {
        uint32_t Ah = sbase + st * STG;
        uint32_t Bh = Ah + A_SZ;
#pragma unroll
        for (int ks = 0; ks < 4; ks++) {
            int acol = (ks * 16 + lsel * 8) * 2;
            int arow = wm + lrow;
            int brow = (ks * 16 + lrow) * 272;
            int bcol0 = (wn + lsel * 8) * 2;
            uint32_t ahi[2][4], bh[4][4];
#pragma unroll
            for (int i = 0; i < 2; i++) ldsm_x4(ahi[i], Ah + (arow + i * 16) * 144 + acol);
#pragma unroll
            for (int j = 0; j < 4; j++) ldsm_x4t(bh[j], Bh + brow + bcol0 + j * 32);
#pragma unroll
            for (int i = 0; i < 2; i++)
#pragma unroll
                for (int jj = 0; jj < 8; jj++)
                    mma_f16(acc[i][jj], ahi[i],
                            bh[jj >> 1][(jj & 1) * 2], bh[jj >> 1][(jj & 1) * 2 + 1]);
        }
    };

    // prologue: stages 0 and 1 in flight
    issue_chunk(0, 0);
    issue_chunk(1, 1);

    int st = 0;
    for (int kc = 0; kc < 32; kc++) {
        if (kc < 30) CP_WAIT1(); else CP_WAIT0();   // chunk kc resident
        __syncthreads();                            // stage (kc-1)%3 free for reuse
        if (kc + 2 < 32) issue_chunk(kc + 2, (st + 2) % 3);
        compute(st);
        st = (st + 1) % 3;
    }

    // ======== fused epilogue: BN+ReLU -> smem F tile -> bilinear gather ========
    __syncthreads();
    float* Fs = (float*)dsm;               // [2 batches][64 hw][128 cf] = 64KB
    {
        int jb = w & 1;
        int gid = lane >> 2, tig = lane & 3;
        float* Fb = Fs + jb * 8192;
#pragma unroll
        for (int i = 0; i < 2; i++) {
            int cfl = wm + i * 16 + gid;
            int cfA = m0 + cfl, cfB = cfA + 8;
            float scA = gam[cfA] * rsqrtf(var[cfA] + EPS_);
            float bbA = bet[cfA] + (cbias[cfA] - mu[cfA]) * scA;
            float scB = gam[cfB] * rsqrtf(var[cfB] + EPS_);
            float bbB = bet[cfB] + (cbias[cfB] - mu[cfB]) * scB;
#pragma unroll
            for (int jj = 0; jj < 8; jj++) {
                int hw = jj * 8 + tig * 2;
                Fb[hw * 128 + cfl]           = fmaxf(fmaf(acc[i][jj][0], scA, bbA), 0.f);
                Fb[(hw + 1) * 128 + cfl]     = fmaxf(fmaf(acc[i][jj][1], scA, bbA), 0.f);
                Fb[hw * 128 + cfl + 8]       = fmaxf(fmaf(acc[i][jj][2], scB, bbB), 0.f);
                Fb[(hw + 1) * 128 + cfl + 8] = fmaxf(fmaf(acc[i][jj][3], scB, bbB), 0.f);
            }
        }
    }
    if (tid < 2 * J_) {
        int bb = tid / J_, j = tid - bb * J_;
        float x = coords[((b0 + bb) * J_ + j) * 3 + 0];
        float y = coords[((b0 + bb) * J_ + j) * 3 + 1];
        float x0f = floorf(x), y0f = floorf(y);
        float wx1 = x - x0f, wy1 = y - y0f;
        float wx0 = 1.f - wx1, wy0 = 1.f - wy1;
        int x0 = (int)x0f, y0 = (int)y0f, x1 = x0 + 1, y1 = y0 + 1;
        int ys[4] = {y0, y0, y1, y1};
        int xs[4] = {x0, x1, x0, x1};
        float ws[4] = {wy0 * wx0, wy0 * wx1, wy1 * wx0, wy1 * wx1};
#pragma unroll
        for (int c = 0; c < 4; c++) {
            bool valid = (xs[c] >= 0) && (xs[c] < 8) && (ys[c] >= 0) && (ys[c] < 8);
            int yc = min(max(ys[c], 0), 7), xc = min(max(xs[c], 0), 7);
            s_gi[bb][j][c] = yc * 8 + xc;
            s_gw[bb][j][c] = valid ? ws[c] : 0.f;
        }
    }
    __syncthreads();
    {
        int bb = tid >> 7, cfl = tid & 127;
        const float* Fg = Fs + bb * 8192 + cfl;
        __half* dst = g_feat_h + (size_t)(b0 + bb) * DP_ + m0 + cfl;
#pragma unroll 5
        for (int j = 0; j < J_; j++) {
            int i0 = s_gi[bb][j][0], i1 = s_gi[bb][j][1];
            int i2 = s_gi[bb][j][2], i3 = s_gi[bb][j][3];
            float v = s_gw[bb][j][0] * Fg[i0 * 128] + s_gw[bb][j][1] * Fg[i1 * 128]
                    + s_gw[bb][j][2] * Fg[i2 * 128] + s_gw[bb][j][3] * Fg[i3 * 128];
            dst[j * JP_] = __float2half(v);
        }
    }
}

// ============================================================
// K3: big heads via mma.sync. grid (8 b-tiles, 15 joint-pair ksplits).
// CTA: 64 batch x 128 out, K=1040 (2 joints, padded). 128 threads (4 warps
// 2m x 2n, warp tile 32x64). 13 chunks of 80. 2-stage cp.async.
// ============================================================
#define MM_ASZ 11264
#define MM_STG 33792
#define SMEM_MM (2 * MM_STG)

__global__ void __launch_bounds__(128) k_bigmm_mma() {
    extern __shared__ __align__(16) char dsm[];
    const int tid = threadIdx.x;
    const int b0 = blockIdx.x * 64;
    const int ks = blockIdx.y;                 // joint pair
    const size_t kbase = (size_t)ks * 2 * JP_;
    const uint32_t sbase = smem_u32(dsm);

    float acc[2][8][4];
#pragma unroll
    for (int i = 0; i < 2; i++)
#pragma unroll
        for (int j = 0; j < 8; j++)
#pragma unroll
            for (int r = 0; r < 4; r++) acc[i][j][r] = 0.f;

    auto issue_chunk = [&](int kc, int nb) {
        int k0 = kc * 80;
        uint32_t abase = sbase + nb * MM_STG;
        uint32_t bbase = abase + MM_ASZ;
#pragma unroll
        for (int t = 0; t < 5; t++) {
            int idx = tid + t * 128;
            int row = idx / 10, q = idx - row * 10;
            const __half* src = g_feat_h + (size_t)(b0 + row) * DP_ + kbase + k0 + q * 8;
            cpa16(abase + row * 176 + q * 16, src);
        }
#pragma unroll
        for (int t = 0; t < 10; t++) {
            int idx = tid + t * 128;
            int row = idx / 10, q = idx - row * 10;
            const __half* src = g_Wbig + (size_t)row * DP_ + kbase + k0 + q * 8;
            cpa16(bbase + row * 176 + q * 16, src);
        }
        CP_COMMIT();
    };

    const int w = tid >> 5, lane = tid & 31;
    const int wm = (w >> 1) * 32;
    const int wn = (w & 1) * 64;
    const int lrow = lane & 15, lsel = lane >> 4;
    const int bn = (lane & 7) | ((lane >> 1) & 8);
    const int bk = (lane >> 3) & 1;

    auto compute = [&](int nb) {
        uint32_t As = sbase + nb * MM_STG;
        uint32_t Bs = As + MM_ASZ;
#pragma unroll
        for (int ks2 = 0; ks2 < 5; ks2++) {
            uint32_t a[2][4], bh[4][4];
#pragma unroll
            for (int i = 0; i < 2; i++)
                ldsm_x4(a[i], As + (wm + lrow + i * 16) * 176 + (ks2 * 16 + lsel * 8) * 2);
#pragma unroll
            for (int j = 0; j < 4; j++)
                ldsm_x4(bh[j], Bs + (wn + j * 16 + bn) * 176 + (ks2 * 16 + bk * 8) * 2);
#pragma unroll
            for (int i = 0; i < 2; i++)
#pragma unroll
                for (int jj = 0; jj < 8; jj++)
                    mma_f16(acc[i][jj], a[i],
                            bh[jj >> 1][(jj & 1) * 2], bh[jj >> 1][(jj & 1) * 2 + 1]);
        }
    };

    issue_chunk(0, 0);
    CP_WAIT0();
    __syncthreads();
    for (int kc = 0; kc < 13; kc++) {
        int nb = kc & 1;
        if (kc < 12) issue_chunk(kc + 1, nb ^ 1);
        compute(nb);
        if (kc < 12) {
            CP_WAIT0();
            __syncthreads();
        }
    }

    int gid = lane >> 2, tig = lane & 3;
    float* P = g_part + (size_t)ks * B_ * 132;
#pragma unroll
    for (int i = 0; i < 2; i++) {
        int mA = b0 + wm + i * 16 + gid, mB = mA + 8;
#pragma unroll
        for (int jj = 0; jj < 8; jj++) {
            int o = wn + jj * 8 + tig * 2;
            P[(size_t)mA * 132 + o]     = acc[i][jj][0];
            P[(size_t)mA * 132 + o + 1] = acc[i][jj][1];
            P[(size_t)mB * 132 + o]     = acc[i][jj][2];
            P[(size_t)mB * 132 + o + 1] = acc[i][jj][3];
        }
    }
}

// ============================================================
// K_tail: pose outputs 122..125 via ksplit partials. grid (8 btiles, 15 jsplits).
// ============================================================
__global__ void __launch_bounds__(256) k_tail(const float* __restrict__ pw) {
    __shared__ float sw_[4][1030];
    int b0 = blockIdx.x * 64;
    int ks = blockIdx.y;
    int j0 = ks * 2;
    for (int t = threadIdx.x; t < 4 * 1030; t += 256) {
        int o = t / 1030, r = t - o * 1030;
        int jj = r / 515, c = r - jj * 515;
        sw_[o][r] = pw[(size_t)(122 + o) * D_ + (j0 + jj) * 515 + c];
    }
    __syncthreads();
    int b = b0 + (threadIdx.x >> 2), o = threadIdx.x & 3;
    const __half* fb = g_feat_h + (size_t)b * DP_ + (size_t)j0 * JP_;
    float s = 0.f;
#pragma unroll 2
    for (int jj = 0; jj < 2; jj++) {
        const __half* fj = fb + jj * JP_;
        const float* wj = sw_[o] + jj * 515;
#pragma unroll 5
        for (int c = 0; c < 515; c++)
            s += __half2float(fj[c]) * wj[c];
    }
    g_part[((size_t)ks * B_ + b) * 132 + 128 + o] = s;
}

// ============================================================
// K_reduce: sum 15 partials for all 132 outputs, add bias
// ============================================================
__global__ void k_reduce(const float* __restrict__ rb, const float* __restrict__ pb,
                         float* __restrict__ out) {
    int i = blockIdx.x * 256 + threadIdx.x;
    if (i >= B_ * 132) return;
    int b = i / 132, o = i - b * 132;
    float s = 0.f;
#pragma unroll
    for (int ks = 0; ks < 15; ks++) s += g_part[(size_t)ks * B_ * 132 + i];
    if (o < 6) out[b * 6 + o] = s + rb[o];
    else       out[3072 + b * 126 + (o - 6)] = s + pb[o - 6];
}

// ============================================================
extern "C" void kernel_launch(void* const* d_in, const int* in_sizes, int n_in,
                              void* d_out, int out_size) {
    const float* img    = (const float*)d_in[0];
    const float* coords = (const float*)d_in[1];
    const float* conv_w = (const float*)d_in[2];
    const float* conv_b = (const float*)d_in[3];
    const float* gam    = (const float*)d_in[4];
    const float* bet    = (const float*)d_in[5];
    const float* mu     = (const float*)d_in[6];
    const float* var    = (const float*)d_in[7];
    const float* root_w = (const float*)d_in[8];
    const float* root_b = (const float*)d_in[9];
    const float* pose_w = (const float*)d_in[10];
    const float* pose_b = (const float*)d_in[11];
    const float* shp_w  = (const float*)d_in[12];
    const float* shp_b  = (const float*)d_in[13];
    const float* cam_w  = (const float*)d_in[14];
    const float* cam_b  = (const float*)d_in[15];
    float* out = (float*)d_out;

    cudaFuncSetAttribute(k_conv_mma, cudaFuncAttributeMaxDynamicSharedMemorySize, SMEM_CONV);
    cudaFuncSetAttribute(k_bigmm_mma, cudaFuncAttributeMaxDynamicSharedMemorySize, SMEM_MM);

    k_prep_w<<<2048, 256>>>(conv_w);
    k_prep_rw<<<(128 * DP_ + 255) / 256, 256>>>(root_w, pose_w);
    k_prep_x<<<65536, 256>>>(img);                   // also computes g_pooled
    k_heads<<<B_, 416>>>(shp_w, shp_b, cam_w, cam_b, coords, out);
    k_conv_mma<<<dim3(4, 256), 256, SMEM_CONV>>>(coords, conv_b, gam, bet, mu, var);
    k_bigmm_mma<<<dim3(8, 15), 128, SMEM_MM>>>();
    k_tail<<<dim3(8, 15), 256>>>(pose_w);
    k_reduce<<<(B_ * 132 + 255) / 256, 256>>>(root_b, pose_b, out);
}

// round 17
// speedup vs baseline: 1.0770x; 1.0183x over previous
#include <cuda_runtime.h>
#include <cuda_fp16.h>
#include <cstdint>
#include <math.h>

// Problem constants
#define B_   512
#define C_   2048
#define HW_  64
#define CF_  512
#define J_   30
#define D_   15450          // J*(CF+3)
#define JP_  520            // padded joint width (fp16, 1040B, 16B aligned)
#define DP_  (J_ * JP_)     // 15600
#define EPS_ 1e-5f

// Output layout (flattened tuple concat):
// root (512*6) @0, pose (512*126) @3072, shape (512*10) @67584, cam (512*3) @72704

// ---- scratch (static device globals; no allocation APIs) ----
__device__ float g_pooled[B_ * C_];                        // 4 MB
__device__ float g_part[(size_t)15 * B_ * 132];            // partials, stride 132
// feat fp16, padded: [b][j][520]
__device__ __align__(256) __half g_feat_h[(size_t)B_ * DP_];        // 16 MB
// big-head weights fp16 (first 128 outputs), padded: [o][j][520]
__device__ __align__(256) __half g_Wbig[(size_t)128 * DP_];         // 4 MB
// conv W fp16: [m=512][k=2048]
__device__ __align__(256) __half g_Wh[(size_t)512 * 2048];          // 2 MB
// X fp16: [b][c][hw]
__device__ __align__(256) __half g_Xh[(size_t)B_ * C_ * HW_];       // 134 MB

// =================== PTX helpers (sm_80+ ISA only) ===================
__device__ __forceinline__ uint32_t smem_u32(const void* p) {
    uint32_t a;
    asm("{ .reg .u64 t; cvta.to.shared.u64 t, %1; cvt.u32.u64 %0, t; }" : "=r"(a) : "l"(p));
    return a;
}
__device__ __forceinline__ void cpa16(uint32_t dst, const void* src) {
    asm volatile("cp.async.cg.shared.global [%0], [%1], 16;" :: "r"(dst), "l"(src));
}
#define CP_COMMIT() asm volatile("cp.async.commit_group;" ::: "memory")
#define CP_WAIT0()  asm volatile("cp.async.wait_group 0;" ::: "memory")

__device__ __forceinline__ void ldsm_x4(uint32_t (&r)[4], uint32_t addr) {
    asm volatile("ldmatrix.sync.aligned.m8n8.x4.shared.b16 {%0,%1,%2,%3}, [%4];"
        : "=r"(r[0]), "=r"(r[1]), "=r"(r[2]), "=r"(r[3]) : "r"(addr));
}
__device__ __forceinline__ void ldsm_x4t(uint32_t (&r)[4], uint32_t addr) {
    asm volatile("ldmatrix.sync.aligned.m8n8.x4.trans.shared.b16 {%0,%1,%2,%3}, [%4];"
        : "=r"(r[0]), "=r"(r[1]), "=r"(r[2]), "=r"(r[3]) : "r"(addr));
}
__device__ __forceinline__ void mma_f16(float (&c)[4], const uint32_t (&a)[4],
                                        uint32_t b0, uint32_t b1) {
    asm volatile("mma.sync.aligned.m16n8k16.row.col.f32.f16.f16.f32 "
        "{%0,%1,%2,%3}, {%4,%5,%6,%7}, {%8,%9}, {%0,%1,%2,%3};"
        : "+f"(c[0]), "+f"(c[1]), "+f"(c[2]), "+f"(c[3])
        : "r"(a[0]), "r"(a[1]), "r"(a[2]), "r"(a[3]), "r"(b0), "r"(b1));
}

// ============================================================
// K_prep_w: conv_w fp32 -> fp16, [m][k] row-major
// ============================================================
__global__ void __launch_bounds__(256) k_prep_w(const float* __restrict__ Wsrc) {
    int i = blockIdx.x * 256 + threadIdx.x;     // over 512*1024 float2
    int m = i >> 10, c2 = i & 1023;
    float2 v = *(const float2*)(Wsrc + (size_t)m * C_ + 2 * c2);
    __half2 ph; ph.x = __float2half(v.x); ph.y = __float2half(v.y);
    *(__half2*)(g_Wh + (size_t)m * 2048 + 2 * c2) = ph;
}

// ============================================================
// K_prep_rw: root_w(6) + pose_w(0..121) -> fp16 padded [128][j][520]
// ============================================================
__global__ void __launch_bounds__(256) k_prep_rw(const float* __restrict__ rw,
                                                 const float* __restrict__ pw) {
    int idx = blockIdx.x * 256 + threadIdx.x;   // over 128*15600
    if (idx >= 128 * DP_) return;
    int o = idx / DP_, r = idx - o * DP_;
    int j = r / JP_, c = r - j * JP_;
    float v = 0.f;
    if (c < 515) {
        const float* wr = (o < 6) ? (rw + (size_t)o * D_) : (pw + (size_t)(o - 6) * D_);
        v = wr[j * 515 + c];
    }
    g_Wbig[idx] = __float2half(v);
}

// ============================================================
// K_prep_x: img fp32 -> fp16 (same layout) + fused global pool
// ============================================================
__global__ void __launch_bounds__(256) k_prep_x(const float* __restrict__ img) {
    size_t i = (size_t)blockIdx.x * 256 + threadIdx.x;   // over 16.8M float4
    float4 v = ((const float4*)img)[i];
    __half2 a; a.x = __float2half(v.x); a.y = __float2half(v.y);
    __half2 b; b.x = __float2half(v.z); b.y = __float2half(v.w);
    *(uint2*)(g_Xh + i * 4) = make_uint2(*(uint32_t*)&a, *(uint32_t*)&b);
    float s = v.x + v.y + v.z + v.w;
#pragma unroll
    for (int off = 1; off < 16; off <<= 1) s += __shfl_xor_sync(0xffffffffu, s, off);
    if ((threadIdx.x & 15) == 0) g_pooled[i >> 4] = s * (1.0f / 64.0f);
}

// ============================================================
// K0b: shape/cam heads (13 warps, warp per output, dual accumulators)
//      + feat coord-tail cols
// ============================================================
__global__ void __launch_bounds__(416) k_heads(
    const float* __restrict__ sw, const float* __restrict__ sb,
    const float* __restrict__ cw, const float* __restrict__ cb,
    const float* __restrict__ coords, float* __restrict__ out) {
    int b = blockIdx.x;
    __shared__ float pr[C_];
    for (int i = threadIdx.x; i < C_; i += 416) pr[i] = g_pooled[b * C_ + i];
    for (int t = threadIdx.x; t < J_ * 8; t += 416) {
        int j = t >> 3, c8 = t & 7;
        float v = (c8 < 3) ? coords[(b * J_ + j) * 3 + c8] : 0.f;
        g_feat_h[(size_t)b * DP_ + j * JP_ + 512 + c8] = __float2half(v);
    }
    __syncthreads();
    int o = threadIdx.x >> 5, l = threadIdx.x & 31;
    const float* wr = (o < 10) ? (sw + (size_t)o * C_) : (cw + (size_t)(o - 10) * C_);
    float s0 = 0.f, s1 = 0.f;
#pragma unroll 8
    for (int k = l; k < C_; k += 64) {
        s0 += pr[k] * wr[k];
        s1 += pr[k + 32] * wr[k + 32];
    }
    float s = s0 + s1;
#pragma unroll
    for (int off = 16; off; off >>= 1) s += __shfl_xor_sync(0xffffffffu, s, off);
    if (l == 0) {
        if (o < 10) out[67584 + b * 10 + o] = s + sb[o];
        else        out[72704 + b * 3 + (o - 10)] = s + cb[o - 10];
    }
}

// ============================================================
// K1: conv GEMM via mma.sync + FUSED bilinear gather -> g_feat_h (fp16)
// (R14 configuration — validated optimum)
// CTA: M=128 cf x N=128 (2 batches x 64 hw), K=2048, 32 chunks of 64.
// 256 threads (8 warps: 4m x 2n, warp tile 32x64), 2 CTAs/SM, 2-stage.
// SMEM per stage 35840 B (A 128x144B; B 64x272B); total 71680 B.
// ============================================================
#define A_SZ  18432
#define STG   35840
#define SMEM_CONV (2 * STG)

__global__ void __launch_bounds__(256, 2) k_conv_mma(
    const float* __restrict__ coords, const float* __restrict__ cbias,
    const float* __restrict__ gam, const float* __restrict__ bet,
    const float* __restrict__ mu, const float* __restrict__ var) {
    extern __shared__ __align__(16) char dsm[];
    __shared__ int   s_gi[2][J_][4];
    __shared__ float s_gw[2][J_][4];
    const int tid = threadIdx.x;
    const int m0 = blockIdx.x * 128;
    const int b0 = blockIdx.y * 2;
    const uint32_t sbase = smem_u32(dsm);

    float acc[2][8][4];
#pragma unroll
    for (int i = 0; i < 2; i++)
#pragma unroll
        for (int j = 0; j < 8; j++)
#pragma unroll
            for (int r = 0; r < 4; r++) acc[i][j][r] = 0.f;

    auto issue_chunk = [&](int kc, int nb) {
        int k0 = kc * 64;
        uint32_t abase = sbase + nb * STG;
        uint32_t bbase = abase + A_SZ;
#pragma unroll
        for (int t = 0; t < 4; t++) {
            int idx = tid + t * 256;
            int row = idx >> 3, q = idx & 7;
            const __half* src = g_Wh + (size_t)(m0 + row) * 2048 + k0 + q * 8;
            cpa16(abase + row * 144 + q * 16, src);
        }
#pragma unroll
        for (int t = 0; t < 4; t++) {
            int idx = tid + t * 256;
            int k = idx >> 4, r = idx & 15;
            int j = r >> 3, hwq = r & 7;
            const __half* src =
                g_Xh + ((size_t)(b0 + j) * C_ + k0 + k) * HW_ + hwq * 8;
            cpa16(bbase + k * 272 + r * 16, src);
        }
        CP_COMMIT();
    };

    const int w = tid >> 5, lane = tid & 31;
    const int wm = (w >> 1) * 32;
    const int wn = (w & 1) * 64;
    const int lrow = lane & 15, lsel = lane >> 4;

    auto compute = [&](int nb) {
        uint32_t Ah = sbase + nb * STG;
        uint32_t Bh = Ah + A_SZ;
#pragma unroll
        for (int ks = 0; ks < 4; ks++) {
            int acol = (ks * 16 + lsel * 8) * 2;
            int arow = wm + lrow;
            int brow = (ks * 16 + lrow) * 272;
            int bcol0 = (wn + lsel * 8) * 2;
            uint32_t ahi[2][4], bh[4][4];
#pragma unroll
            for (int i = 0; i < 2; i++) ldsm_x4(ahi[i], Ah + (arow + i * 16) * 144 + acol);
#pragma unroll
            for (int j = 0; j < 4; j++) ldsm_x4t(bh[j], Bh + brow + bcol0 + j * 32);
#pragma unroll
            for (int i = 0; i < 2; i++)
#pragma unroll
                for (int jj = 0; jj < 8; jj++)
                    mma_f16(acc[i][jj], ahi[i],
                            bh[jj >> 1][(jj & 1) * 2], bh[jj >> 1][(jj & 1) * 2 + 1]);
        }
    };

    issue_chunk(0, 0);
    CP_WAIT0();
    __syncthreads();

    for (int kc = 0; kc < 32; kc++) {
        int nb = kc & 1;
        if (kc < 31) issue_chunk(kc + 1, nb ^ 1);
        compute(nb);
        if (kc < 31) {
            CP_WAIT0();
            __syncthreads();
        }
    }

    // ======== fused epilogue: BN+ReLU -> smem F tile -> bilinear gather ========
    __syncthreads();
    float* Fs = (float*)dsm;               // [2 batches][64 hw][128 cf] = 64KB
    {
        int jb = w & 1;
        int gid = lane >> 2, tig = lane & 3;
        float* Fb = Fs + jb * 8192;
#pragma unroll
        for (int i = 0; i < 2; i++) {
            int cfl = wm + i * 16 + gid;
            int cfA = m0 + cfl, cfB = cfA + 8;
            float scA = gam[cfA] * rsqrtf(var[cfA] + EPS_);
            float bbA = bet[cfA] + (cbias[cfA] - mu[cfA]) * scA;
            float scB = gam[cfB] * rsqrtf(var[cfB] + EPS_);
            float bbB = bet[cfB] + (cbias[cfB] - mu[cfB]) * scB;
#pragma unroll
            for (int jj = 0; jj < 8; jj++) {
                int hw = jj * 8 + tig * 2;
                Fb[hw * 128 + cfl]           = fmaxf(fmaf(acc[i][jj][0], scA, bbA), 0.f);
                Fb[(hw + 1) * 128 + cfl]     = fmaxf(fmaf(acc[i][jj][1], scA, bbA), 0.f);
                Fb[hw * 128 + cfl + 8]       = fmaxf(fmaf(acc[i][jj][2], scB, bbB), 0.f);
                Fb[(hw + 1) * 128 + cfl + 8] = fmaxf(fmaf(acc[i][jj][3], scB, bbB), 0.f);
            }
        }
    }
    if (tid < 2 * J_) {
        int bb = tid / J_, j = tid - bb * J_;
        float x = coords[((b0 + bb) * J_ + j) * 3 + 0];
        float y = coords[((b0 + bb) * J_ + j) * 3 + 1];
        float x0f = floorf(x), y0f = floorf(y);
        float wx1 = x - x0f, wy1 = y - y0f;
        float wx0 = 1.f - wx1, wy0 = 1.f - wy1;
        int x0 = (int)x0f, y0 = (int)y0f, x1 = x0 + 1, y1 = y0 + 1;
        int ys[4] = {y0, y0, y1, y1};
        int xs[4] = {x0, x1, x0, x1};
        float ws[4] = {wy0 * wx0, wy0 * wx1, wy1 * wx0, wy1 * wx1};
#pragma unroll
        for (int c = 0; c < 4; c++) {
            bool valid = (xs[c] >= 0) && (xs[c] < 8) && (ys[c] >= 0) && (ys[c] < 8);
            int yc = min(max(ys[c], 0), 7), xc = min(max(xs[c], 0), 7);
            s_gi[bb][j][c] = yc * 8 + xc;
            s_gw[bb][j][c] = valid ? ws[c] : 0.f;
        }
    }
    __syncthreads();
    {
        int bb = tid >> 7, cfl = tid & 127;
        const float* Fg = Fs + bb * 8192 + cfl;
        __half* dst = g_feat_h + (size_t)(b0 + bb) * DP_ + m0 + cfl;
#pragma unroll 5
        for (int j = 0; j < J_; j++) {
            int i0 = s_gi[bb][j][0], i1 = s_gi[bb][j][1];
            int i2 = s_gi[bb][j][2], i3 = s_gi[bb][j][3];
            float v = s_gw[bb][j][0] * Fg[i0 * 128] + s_gw[bb][j][1] * Fg[i1 * 128]
                    + s_gw[bb][j][2] * Fg[i2 * 128] + s_gw[bb][j][3] * Fg[i3 * 128];
            dst[j * JP_] = __float2half(v);
        }
    }
}

// ============================================================
// K3: big heads via mma.sync. grid (8 b-tiles, 15 joint-pair ksplits).
// CTA: 64 batch x 128 out, K=1040 (2 joints, padded). 128 threads (4 warps
// 2m x 2n, warp tile 32x64). 13 chunks of 80. 2-stage cp.async.
// ============================================================
#define MM_ASZ 11264
#define MM_STG 33792
#define SMEM_MM (2 * MM_STG)

__global__ void __launch_bounds__(128) k_bigmm_mma() {
    extern __shared__ __align__(16) char dsm[];
    const int tid = threadIdx.x;
    const int b0 = blockIdx.x * 64;
    const int ks = blockIdx.y;                 // joint pair
    const size_t kbase = (size_t)ks * 2 * JP_;
    const uint32_t sbase = smem_u32(dsm);

    float acc[2][8][4];
#pragma unroll
    for (int i = 0; i < 2; i++)
#pragma unroll
        for (int j = 0; j < 8; j++)
#pragma unroll
            for (int r = 0; r < 4; r++) acc[i][j][r] = 0.f;

    auto issue_chunk = [&](int kc, int nb) {
        int k0 = kc * 80;
        uint32_t abase = sbase + nb * MM_STG;
        uint32_t bbase = abase + MM_ASZ;
#pragma unroll
        for (int t = 0; t < 5; t++) {
            int idx = tid + t * 128;
            int row = idx / 10, q = idx - row * 10;
            const __half* src = g_feat_h + (size_t)(b0 + row) * DP_ + kbase + k0 + q * 8;
            cpa16(abase + row * 176 + q * 16, src);
        }
#pragma unroll
        for (int t = 0; t < 10; t++) {
            int idx = tid + t * 128;
            int row = idx / 10, q = idx - row * 10;
            const __half* src = g_Wbig + (size_t)row * DP_ + kbase + k0 + q * 8;
            cpa16(bbase + row * 176 + q * 16, src);
        }
        CP_COMMIT();
    };

    const int w = tid >> 5, lane = tid & 31;
    const int wm = (w >> 1) * 32;
    const int wn = (w & 1) * 64;
    const int lrow = lane & 15, lsel = lane >> 4;
    const int bn = (lane & 7) | ((lane >> 1) & 8);
    const int bk = (lane >> 3) & 1;

    auto compute = [&](int nb) {
        uint32_t As = sbase + nb * MM_STG;
        uint32_t Bs = As + MM_ASZ;
#pragma unroll
        for (int ks2 = 0; ks2 < 5; ks2++) {
            uint32_t a[2][4], bh[4][4];
#pragma unroll
            for (int i = 0; i < 2; i++)
                ldsm_x4(a[i], As + (wm + lrow + i * 16) * 176 + (ks2 * 16 + lsel * 8) * 2);
#pragma unroll
            for (int j = 0; j < 4; j++)
                ldsm_x4(bh[j], Bs + (wn + j * 16 + bn) * 176 + (ks2 * 16 + bk * 8) * 2);
#pragma unroll
            for (int i = 0; i < 2; i++)
#pragma unroll
                for (int jj = 0; jj < 8; jj++)
                    mma_f16(acc[i][jj], a[i],
                            bh[jj >> 1][(jj & 1) * 2], bh[jj >> 1][(jj & 1) * 2 + 1]);
        }
    };

    issue_chunk(0, 0);
    CP_WAIT0();
    __syncthreads();
    for (int kc = 0; kc < 13; kc++) {
        int nb = kc & 1;
        if (kc < 12) issue_chunk(kc + 1, nb ^ 1);
        compute(nb);
        if (kc < 12) {
            CP_WAIT0();
            __syncthreads();
        }
    }

    int gid = lane >> 2, tig = lane & 3;
    float* P = g_part + (size_t)ks * B_ * 132;
#pragma unroll
    for (int i = 0; i < 2; i++) {
        int mA = b0 + wm + i * 16 + gid, mB = mA + 8;
#pragma unroll
        for (int jj = 0; jj < 8; jj++) {
            int o = wn + jj * 8 + tig * 2;
            P[(size_t)mA * 132 + o]     = acc[i][jj][0];
            P[(size_t)mA * 132 + o + 1] = acc[i][jj][1];
            P[(size_t)mB * 132 + o]     = acc[i][jj][2];
            P[(size_t)mB * 132 + o + 1] = acc[i][jj][3];
        }
    }
}

// ============================================================
// K_tail: pose outputs 122..125 via ksplit partials. grid (8 btiles, 15 jsplits).
// ============================================================
__global__ void __launch_bounds__(256) k_tail(const float* __restrict__ pw) {
    __shared__ float sw_[4][1030];
    int b0 = blockIdx.x * 64;
    int ks = blockIdx.y;
    int j0 = ks * 2;
    for (int t = threadIdx.x; t < 4 * 1030; t += 256) {
        int o = t / 1030, r = t - o * 1030;
        int jj = r / 515, c = r - jj * 515;
        sw_[o][r] = pw[(size_t)(122 + o) * D_ + (j0 + jj) * 515 + c];
    }
    __syncthreads();
    int b = b0 + (threadIdx.x >> 2), o = threadIdx.x & 3;
    const __half* fb = g_feat_h + (size_t)b * DP_ + (size_t)j0 * JP_;
    float s = 0.f;
#pragma unroll 2
    for (int jj = 0; jj < 2; jj++) {
        const __half* fj = fb + jj * JP_;
        const float* wj = sw_[o] + jj * 515;
#pragma unroll 5
        for (int c = 0; c < 515; c++)
            s += __half2float(fj[c]) * wj[c];
    }
    g_part[((size_t)ks * B_ + b) * 132 + 128 + o] = s;
}

// ============================================================
// K_reduce: sum 15 partials for all 132 outputs, add bias
// ============================================================
__global__ void k_reduce(const float* __restrict__ rb, const float* __restrict__ pb,
                         float* __restrict__ out) {
    int i = blockIdx.x * 256 + threadIdx.x;
    if (i >= B_ * 132) return;
    int b = i / 132, o = i - b * 132;
    float s = 0.f;
#pragma unroll
    for (int ks = 0; ks < 15; ks++) s += g_part[(size_t)ks * B_ * 132 + i];
    if (o < 6) out[b * 6 + o] = s + rb[o];
    else       out[3072 + b * 126 + (o - 6)] = s + pb[o - 6];
}

// ============================================================
extern "C" void kernel_launch(void* const* d_in, const int* in_sizes, int n_in,
                              void* d_out, int out_size) {
    const float* img    = (const float*)d_in[0];
    const float* coords = (const float*)d_in[1];
    const float* conv_w = (const float*)d_in[2];
    const float* conv_b = (const float*)d_in[3];
    const float* gam    = (const float*)d_in[4];
    const float* bet    = (const float*)d_in[5];
    const float* mu     = (const float*)d_in[6];
    const float* var    = (const float*)d_in[7];
    const float* root_w = (const float*)d_in[8];
    const float* root_b = (const float*)d_in[9];
    const float* pose_w = (const float*)d_in[10];
    const float* pose_b = (const float*)d_in[11];
    const float* shp_w  = (const float*)d_in[12];
    const float* shp_b  = (const float*)d_in[13];
    const float* cam_w  = (const float*)d_in[14];
    const float* cam_b  = (const float*)d_in[15];
    float* out = (float*)d_out;

    cudaFuncSetAttribute(k_conv_mma, cudaFuncAttributeMaxDynamicSharedMemorySize, SMEM_CONV);
    cudaFuncSetAttribute(k_bigmm_mma, cudaFuncAttributeMaxDynamicSharedMemorySize, SMEM_MM);

    k_prep_w<<<2048, 256>>>(conv_w);
    k_prep_rw<<<(128 * DP_ + 255) / 256, 256>>>(root_w, pose_w);
    k_prep_x<<<65536, 256>>>(img);                   // also computes g_pooled
    k_heads<<<B_, 416>>>(shp_w, shp_b, cam_w, cam_b, coords, out);
    k_conv_mma<<<dim3(4, 256), 256, SMEM_CONV>>>(coords, conv_b, gam, bet, mu, var);
    k_bigmm_mma<<<dim3(8, 15), 128, SMEM_MM>>>();
    k_tail<<<dim3(8, 15), 256>>>(pose_w);
    k_reduce<<<(B_ * 132 + 255) / 256, 256>>>(root_b, pose_b, out);
}